// round 9
// baseline (speedup 1.0000x reference)
#include <cuda_runtime.h>

// CARAFE: features [2,64,64,256] f32, masks [2,128,128,25] f32, k=5, group=1.
// Nearest 64->128 half-pixel => src = dst >> 1; each source pixel feeds a 2x2
// output block sharing its 5x5 patch.
// R9: R8 + two-deep mask register pipeline. d-major tap groups (group g uses
//     one window column slot); while FFMAing group g from mcur[5], the next
//     group's 5 mask float4s load into mnext[5] -> every mask LDS has ~40 FFMA
//     slots before first use. Window refill LDG consumed ~180 slots later.

#define FH 64
#define FW 64
#define C2 128     // 256 channels / 2 (float2 groups)
#define OH 128
#define OW 128
#define KK 25
#define SEGW 8

__device__ __forceinline__ void fma2s(float2& a, const float2 f, const float m) {
    a.x = fmaf(f.x, m, a.x);
    a.y = fmaf(f.y, m, a.y);
}

template<bool CHK>
__device__ __forceinline__ void carafe_body(int seg, int hs, int b,
                                            const float2* __restrict__ F,
                                            float2* __restrict__ O,
                                            const float* __restrict__ smask,
                                            int c2)
{
    const int ws0 = seg * SEGW;
    const float2 z = make_float2(0.f, 0.f);

    // single feature base at (row hs-2, col ws0-2); all accesses below are
    // compile-time immediate offsets.
    const float2* fb = F + ((b * FH + (hs - 2)) * FW + (ws0 - 2)) * C2 + c2;

    bool rok[5];
    #pragma unroll
    for (int r = 0; r < 5; r++) {
        int hr = hs - 2 + r;
        rok[r] = CHK ? (hr >= 0 && hr < FH) : true;
    }

    // 5-slot rotating window: col (ws0-2+j) -> slot j (mod 5)
    float2 w[5][5];
    #pragma unroll
    for (int j = 0; j < 5; j++) {
        bool cok = CHK ? ((ws0 - 2 + j) >= 0 && (ws0 - 2 + j) < FW) : true;
        #pragma unroll
        for (int r = 0; r < 5; r++)
            w[r][j] = (rok[r] && cok) ? fb[(r * FW + j) * C2] : z;
    }

    float2* ob = O + ((b * OH + 2 * hs) * OW + 2 * ws0) * C2 + c2;

    // mask pipeline: smask viewed as float4[pixel(8)][pp(25)]
    const float4* __restrict__ mp = (const float4*)smask;

    float4 mcur[5], mnext[5];
    #pragma unroll
    for (int t = 0; t < 5; t++) mcur[t] = mp[t];   // pixel 0, group 0

    #pragma unroll
    for (int s = 0; s < SEGW; s++) {
        float2 a0 = z, a1 = z, a2 = z, a3 = z;

        #pragma unroll
        for (int g = 0; g < 5; g++) {
            // prefetch next 5-tap group (or next pixel's group 0)
            if (g < 4) {
                #pragma unroll
                for (int t = 0; t < 5; t++)
                    mnext[t] = mp[s * KK + (g + 1) * 5 + t];
            } else if (s < SEGW - 1) {
                #pragma unroll
                for (int t = 0; t < 5; t++)
                    mnext[t] = mp[(s + 1) * KK + t];
            }

            // group g: taps pp=g*5+t (d=g, r=t) all read window slot (s+g)%5
            #pragma unroll
            for (int t = 0; t < 5; t++) {
                const float2 f = w[t][(s + g) % 5];   // compile-time slot
                fma2s(a0, f, mcur[t].x);
                fma2s(a1, f, mcur[t].y);
                fma2s(a2, f, mcur[t].z);
                fma2s(a3, f, mcur[t].w);
            }

            #pragma unroll
            for (int t = 0; t < 5; t++) mcur[t] = mnext[t];   // renames
        }

        ob[(2 * s) * C2]          = a0;
        ob[(2 * s + 1) * C2]      = a1;
        ob[(OW + 2 * s) * C2]     = a2;
        ob[(OW + 2 * s + 1) * C2] = a3;

        if (s < SEGW - 1) {
            // refill col (ws0+s+3) into slot s%5; first consumed at iter s+1,
            // group g=4 (the final 40-FFMA burst) -> latency fully covered.
            const bool cok = CHK ? ((ws0 + s + 3) < FW) : true;
            #pragma unroll
            for (int r = 0; r < 5; r++)
                w[r][s % 5] = (rok[r] && cok) ? fb[(r * FW + (s + 5)) * C2] : z;
        }
    }
}

__global__ __launch_bounds__(128)
void carafe_kernel(const float* __restrict__ features,
                   const float* __restrict__ masks,
                   float* __restrict__ out)
{
    // smask layout: [px(8)][pp(25)][out(4)], pp = d*5+r (d-major), out = oy*2+ox
    __shared__ __align__(16) float smask[SEGW * KK * 4];

    const int tid = threadIdx.x;
    const int seg = blockIdx.x;
    const int hs  = blockIdx.y;
    const int b   = blockIdx.z;
    const int ws0 = seg * SEGW;

    // cooperative mask stage with tap permutation r*5+d -> d*5+r
    {
        const int mrow0 = ((b * OH + 2 * hs    ) * OW + 2 * ws0) * KK;
        const int mrow1 = ((b * OH + 2 * hs + 1) * OW + 2 * ws0) * KK;
        #pragma unroll
        for (int it = 0; it < 7; it++) {
            int idx = tid + it * 128;
            if (idx < 800) {
                int oy   = idx / 400;
                int j    = idx - oy * 400;     // contiguous in global mask row
                int wrel = j / KK;             // 0..15 output col in segment
                int p    = j - wrel * KK;      // source tap index (r*5+d)
                int r    = p / 5;
                int d    = p - r * 5;
                int pp   = d * 5 + r;          // d-major position
                int px   = wrel >> 1;
                int ox   = wrel & 1;
                float v = masks[(oy ? mrow1 : mrow0) + j];
                smask[px * (KK * 4) + pp * 4 + oy * 2 + ox] = v;
            }
        }
    }
    __syncthreads();

    const float2* F = (const float2*)features;
    float2* O = (float2*)out;

    const bool interior = (seg >= 1) && (seg <= 6) && (hs >= 2) && (hs <= 61);
    if (interior)
        carafe_body<false>(seg, hs, b, F, O, smask, tid);
    else
        carafe_body<true>(seg, hs, b, F, O, smask, tid);
}

extern "C" void kernel_launch(void* const* d_in, const int* in_sizes, int n_in,
                              void* d_out, int out_size) {
    const float* features = (const float*)d_in[0];
    const float* masks    = (const float*)d_in[1];
    float* out            = (float*)d_out;

    dim3 grid(FW / SEGW, FH, 2);   // (8, 64, 2) = 1024 blocks x 4 warps
    carafe_kernel<<<grid, 128>>>(features, masks, out);
}

// round 10
// speedup vs baseline: 1.1366x; 1.1366x over previous
#include <cuda_runtime.h>

// CARAFE: features [2,64,64,256] f32, masks [2,128,128,25] f32, k=5, group=1.
// Nearest 64->128 half-pixel => src = dst >> 1; each source pixel feeds a 2x2
// output block sharing its 5x5 patch.
// R10: R8 body (5-slot rotating float2 window, d-major taps, immediate offsets,
//      interior/border split) + division-free mask staging: thread (px,o,q)
//      copies taps p = q+4k with compile-time offsets; the d-major permutation
//      moves to consume time (still immediate LDS offsets). Removes ~180
//      serial prologue issues per warp.

#define FH 64
#define FW 64
#define C2 128     // 256 channels / 2 (float2 groups)
#define OH 128
#define OW 128
#define KK 25
#define SEGW 8

__device__ __forceinline__ void fma2s(float2& a, const float2 f, const float m) {
    a.x = fmaf(f.x, m, a.x);
    a.y = fmaf(f.y, m, a.y);
}

template<bool CHK>
__device__ __forceinline__ void carafe_body(int seg, int hs, int b,
                                            const float2* __restrict__ F,
                                            float2* __restrict__ O,
                                            const float* __restrict__ smask,
                                            int c2)
{
    const int ws0 = seg * SEGW;
    const float2 z = make_float2(0.f, 0.f);

    // single feature base at (row hs-2, col ws0-2); all accesses below are
    // compile-time immediate offsets.
    const float2* fb = F + ((b * FH + (hs - 2)) * FW + (ws0 - 2)) * C2 + c2;

    bool rok[5];
    #pragma unroll
    for (int r = 0; r < 5; r++) {
        int hr = hs - 2 + r;
        rok[r] = CHK ? (hr >= 0 && hr < FH) : true;
    }

    // 5-slot rotating window: col (ws0-2+j) -> slot j (mod 5)
    float2 w[5][5];
    #pragma unroll
    for (int j = 0; j < 5; j++) {
        bool cok = CHK ? ((ws0 - 2 + j) >= 0 && (ws0 - 2 + j) < FW) : true;
        #pragma unroll
        for (int r = 0; r < 5; r++)
            w[r][j] = (rok[r] && cok) ? fb[(r * FW + j) * C2] : z;
    }

    float2* ob = O + ((b * OH + 2 * hs) * OW + 2 * ws0) * C2 + c2;

    #pragma unroll
    for (int s = 0; s < SEGW; s++) {
        // smask pixel s, taps in SOURCE order p = r*5+d; float4 per tap (4 outputs)
        const float4* __restrict__ mp = (const float4*)(smask + s * (KK * 4));

        float2 a0 = z, a1 = z, a2 = z, a3 = z;

        // d-major sweep: column slot refilled at end of iter s-1 (d=4 here)
        // is consumed only in the last 5 taps. Permutation applied via the
        // immediate LDS offset r*5+d (compile-time).
        #pragma unroll
        for (int d = 0; d < 5; d++) {
            #pragma unroll
            for (int r = 0; r < 5; r++) {
                const float2 f = w[r][(s + d) % 5];   // compile-time slot
                const float4 m = mp[r * 5 + d];       // broadcast LDS.128
                fma2s(a0, f, m.x);
                fma2s(a1, f, m.y);
                fma2s(a2, f, m.z);
                fma2s(a3, f, m.w);
            }
        }

        ob[(2 * s) * C2]          = a0;
        ob[(2 * s + 1) * C2]      = a1;
        ob[(OW + 2 * s) * C2]     = a2;
        ob[(OW + 2 * s + 1) * C2] = a3;

        if (s < SEGW - 1) {
            // refill col (ws0+s+3) into slot s%5; first consumed at iter s+1,
            // d=4 (the final 40-FFMA burst) -> LDG latency fully covered.
            const bool cok = CHK ? ((ws0 + s + 3) < FW) : true;
            #pragma unroll
            for (int r = 0; r < 5; r++)
                w[r][s % 5] = (rok[r] && cok) ? fb[(r * FW + (s + 5)) * C2] : z;
        }
    }
}

__global__ __launch_bounds__(128)
void carafe_kernel(const float* __restrict__ features,
                   const float* __restrict__ masks,
                   float* __restrict__ out)
{
    // smask layout: [px(8)][p(25)][out(4)], p = r*5+d (source order), out = oy*2+ox
    __shared__ __align__(16) float smask[SEGW * KK * 4];

    const int tid = threadIdx.x;
    const int seg = blockIdx.x;
    const int hs  = blockIdx.y;
    const int b   = blockIdx.z;
    const int ws0 = seg * SEGW;

    // ---- division-free mask transpose stage ----
    // thread decomposition: tid = px*16 + o*4 + q   (px:0..7, o:0..3, q:0..3)
    // thread copies taps p = q + 4k, k = 0..6 (p < 25), all offsets immediate.
    {
        const int q  = tid & 3;
        const int o  = (tid >> 2) & 3;
        const int px = tid >> 4;
        const int oy = o >> 1;
        const int ox = o & 1;

        // global: masks[b, 2*hs+oy, 2*(ws0+px)+ox, :25]
        const float* gm = masks
            + ((b * OH + 2 * hs + oy) * OW + 2 * (ws0 + px) + ox) * KK + q;
        // shared: &smask[px*100 + p*4 + o], stepping p by 4 -> stride 16 floats
        float* sm = smask + px * (KK * 4) + q * 4 + o;

        #pragma unroll
        for (int k = 0; k < 7; k++) {
            if (k < 6 || q == 0)               // p = q+24 valid only for q==0
                sm[k * 16] = gm[k * 4];
        }
    }
    __syncthreads();

    const float2* F = (const float2*)features;
    float2* O = (float2*)out;

    const bool interior = (seg >= 1) && (seg <= 6) && (hs >= 2) && (hs <= 61);
    if (interior)
        carafe_body<false>(seg, hs, b, F, O, smask, tid);
    else
        carafe_body<true>(seg, hs, b, F, O, smask, tid);
}

extern "C" void kernel_launch(void* const* d_in, const int* in_sizes, int n_in,
                              void* d_out, int out_size) {
    const float* features = (const float*)d_in[0];
    const float* masks    = (const float*)d_in[1];
    float* out            = (float*)d_out;

    dim3 grid(FW / SEGW, FH, 2);   // (8, 64, 2) = 1024 blocks x 4 warps
    carafe_kernel<<<grid, 128>>>(features, masks, out);
}